// round 14
// baseline (speedup 1.0000x reference)
#include <cuda_runtime.h>
#include <cuda_fp16.h>
#include <cstdint>

#define SEQ   2048
#define DIM   512
#define NH    8
#define DEPTH 64
#define NB    2
typedef unsigned long long u64;

#define C1    0.18033688011112043f     /* 0.125 * log2(e) */

// ---------------- scratch (device globals; no runtime allocation) ------------
__device__ float    g_qp[(size_t)NB * SEQ * DIM];
__device__ float    g_kp[(size_t)NB * SEQ * DIM];
__device__ float    g_vp[(size_t)NB * SEQ * DIM];
__device__ float    g_attn[(size_t)NB * SEQ * DIM];
__device__ __half   g_qer16[(size_t)NB * NH * SEQ * 1024 + 8];  // 64 MB (+pad for window loads)
__device__ uint32_t g_mb[(size_t)NB * SEQ * (SEQ / 32)];        // 2 MB mask bits

// ---------------- packed fp32x2 helpers (FFMA2: 2x fp32 throughput) ----------
__device__ __forceinline__ u64 pk(float lo, float hi) {
    u64 r; asm("mov.b64 %0,{%1,%2};" : "=l"(r) : "f"(lo), "f"(hi)); return r;
}
__device__ __forceinline__ void fma2(u64& d, u64 a, u64 b) {
    asm("fma.rn.f32x2 %0,%1,%2,%0;" : "+l"(d) : "l"(a), "l"(b));
}
__device__ __forceinline__ float2 up(u64 v) {
    float2 r; asm("mov.b64 {%0,%1},%2;" : "=f"(r.x), "=f"(r.y) : "l"(v)); return r;
}
__device__ __forceinline__ uint32_t s2u(const void* p) {
    uint32_t a;
    asm("{ .reg .u64 t; cvta.to.shared.u64 t, %1; cvt.u32.u64 %0, t; }"
        : "=r"(a) : "l"(p));
    return a;
}
__device__ __forceinline__ void cpasync16(uint32_t sm, const void* g) {
    asm volatile("cp.async.cg.shared.global [%0], [%1], 16;" :: "r"(sm), "l"(g));
}

// ---------------- fast exp2 on the FMA pipe (no MUFU, no F2I) ----------------
__device__ __forceinline__ float fexp2(float y) {
    float t = y + 12582912.0f;           // 1.5 * 2^23 : round-to-nearest int
    float r = t - 12582912.0f;
    float f = y - r;                     // f in [-0.5, 0.5]
    float p = 1.3333558146e-3f;
    p = fmaf(p, f, 9.6181291076e-3f);
    p = fmaf(p, f, 5.5504108664e-2f);
    p = fmaf(p, f, 2.4022650696e-1f);
    p = fmaf(p, f, 6.9314718056e-1f);
    p = fmaf(p, f, 1.0f);
    int R = __float_as_int(t) - 0x4B400000;         // = (int)r
    return p * __int_as_float((R + 127) << 23);
}

// ---------------- 128x128 NT GEMM body, 8x8 microtile, double-buffered -------
__device__ __forceinline__ void gemm128_body(
    const float* __restrict__ A, int lda,
    const float* __restrict__ B, int ldb,
    const float* __restrict__ bias,
    float* __restrict__ C, __half* __restrict__ C16, float cscale,
    int ldc, int K, float* As, float* Bs)
{
    const int tid = threadIdx.x;
    const int tx = tid & 15, ty = tid >> 4;
    const int m0 = blockIdx.y * 128, n0 = blockIdx.x * 128;
    const int lrow = tid >> 2, lc4 = (tid & 3) * 4;
    const float* Ag = A + (size_t)(m0 + lrow) * lda + lc4;
    const float* Bg = B + (size_t)(n0 + lrow) * ldb + lc4;

    u64 acc[8][4];
    #pragma unroll
    for (int i = 0; i < 8; i++)
        #pragma unroll
        for (int j = 0; j < 4; j++) acc[i][j] = 0ull;

    float4 a0 = *(const float4*)(Ag);
    float4 a1 = *(const float4*)(Ag + (size_t)64 * lda);
    float4 b0 = *(const float4*)(Bg);
    float4 b1 = *(const float4*)(Bg + (size_t)64 * ldb);

    As[(lc4 + 0) * 128 + lrow] = a0.x; As[(lc4 + 1) * 128 + lrow] = a0.y;
    As[(lc4 + 2) * 128 + lrow] = a0.z; As[(lc4 + 3) * 128 + lrow] = a0.w;
    As[(lc4 + 0) * 128 + lrow + 64] = a1.x; As[(lc4 + 1) * 128 + lrow + 64] = a1.y;
    As[(lc4 + 2) * 128 + lrow + 64] = a1.z; As[(lc4 + 3) * 128 + lrow + 64] = a1.w;
    Bs[(lc4 + 0) * 128 + lrow] = b0.x; Bs[(lc4 + 1) * 128 + lrow] = b0.y;
    Bs[(lc4 + 2) * 128 + lrow] = b0.z; Bs[(lc4 + 3) * 128 + lrow] = b0.w;
    Bs[(lc4 + 0) * 128 + lrow + 64] = b1.x; Bs[(lc4 + 1) * 128 + lrow + 64] = b1.y;
    Bs[(lc4 + 2) * 128 + lrow + 64] = b1.z; Bs[(lc4 + 3) * 128 + lrow + 64] = b1.w;
    __syncthreads();

    const int nk = K >> 4;
    for (int it = 0; it < nk; it++) {
        const int cb = (it & 1) << 11;
        if (it + 1 < nk) {
            int k0 = (it + 1) << 4;
            a0 = *(const float4*)(Ag + k0);
            a1 = *(const float4*)(Ag + (size_t)64 * lda + k0);
            b0 = *(const float4*)(Bg + k0);
            b1 = *(const float4*)(Bg + (size_t)64 * ldb + k0);
        }
        #pragma unroll
        for (int kk = 0; kk < 16; kk++) {
            float4 x0 = *(const float4*)&As[cb + kk * 128 + ty * 8];
            float4 x1 = *(const float4*)&As[cb + kk * 128 + ty * 8 + 4];
            float4 y0 = *(const float4*)&Bs[cb + kk * 128 + tx * 8];
            float4 y1 = *(const float4*)&Bs[cb + kk * 128 + tx * 8 + 4];
            u64 bp0 = pk(y0.x, y0.y), bp1 = pk(y0.z, y0.w);
            u64 bp2 = pk(y1.x, y1.y), bp3 = pk(y1.z, y1.w);
            float av[8] = {x0.x, x0.y, x0.z, x0.w, x1.x, x1.y, x1.z, x1.w};
            #pragma unroll
            for (int i = 0; i < 8; i++) {
                u64 as = pk(av[i], av[i]);
                fma2(acc[i][0], as, bp0);
                fma2(acc[i][1], as, bp1);
                fma2(acc[i][2], as, bp2);
                fma2(acc[i][3], as, bp3);
            }
        }
        if (it + 1 < nk) {
            const int nb = ((it + 1) & 1) << 11;
            As[nb + (lc4 + 0) * 128 + lrow] = a0.x; As[nb + (lc4 + 1) * 128 + lrow] = a0.y;
            As[nb + (lc4 + 2) * 128 + lrow] = a0.z; As[nb + (lc4 + 3) * 128 + lrow] = a0.w;
            As[nb + (lc4 + 0) * 128 + lrow + 64] = a1.x; As[nb + (lc4 + 1) * 128 + lrow + 64] = a1.y;
            As[nb + (lc4 + 2) * 128 + lrow + 64] = a1.z; As[nb + (lc4 + 3) * 128 + lrow + 64] = a1.w;
            Bs[nb + (lc4 + 0) * 128 + lrow] = b0.x; Bs[nb + (lc4 + 1) * 128 + lrow] = b0.y;
            Bs[nb + (lc4 + 2) * 128 + lrow] = b0.z; Bs[nb + (lc4 + 3) * 128 + lrow] = b0.w;
            Bs[nb + (lc4 + 0) * 128 + lrow + 64] = b1.x; Bs[nb + (lc4 + 1) * 128 + lrow + 64] = b1.y;
            Bs[nb + (lc4 + 2) * 128 + lrow + 64] = b1.z; Bs[nb + (lc4 + 3) * 128 + lrow + 64] = b1.w;
            __syncthreads();
        }
    }

    if (C16) {
        #pragma unroll
        for (int i = 0; i < 8; i++) {
            float2 c0 = up(acc[i][0]), c1 = up(acc[i][1]);
            float2 c2 = up(acc[i][2]), c3 = up(acc[i][3]);
            __half2 h0 = __floats2half2_rn(c0.x * cscale, c0.y * cscale);
            __half2 h1 = __floats2half2_rn(c1.x * cscale, c1.y * cscale);
            __half2 h2 = __floats2half2_rn(c2.x * cscale, c2.y * cscale);
            __half2 h3 = __floats2half2_rn(c3.x * cscale, c3.y * cscale);
            uint4 o;
            o.x = *(uint32_t*)&h0; o.y = *(uint32_t*)&h1;
            o.z = *(uint32_t*)&h2; o.w = *(uint32_t*)&h3;
            *(uint4*)(C16 + (size_t)(m0 + ty * 8 + i) * ldc + n0 + tx * 8) = o;
        }
    } else {
        float bj[8];
        #pragma unroll
        for (int j = 0; j < 8; j++) bj[j] = bias ? bias[n0 + tx * 8 + j] : 0.0f;
        #pragma unroll
        for (int i = 0; i < 8; i++) {
            float2 c0 = up(acc[i][0]), c1 = up(acc[i][1]);
            float2 c2 = up(acc[i][2]), c3 = up(acc[i][3]);
            float4 o0 = {c0.x + bj[0], c0.y + bj[1], c1.x + bj[2], c1.y + bj[3]};
            float4 o1 = {c2.x + bj[4], c2.y + bj[5], c3.x + bj[6], c3.y + bj[7]};
            float* Cr = C + (size_t)(m0 + ty * 8 + i) * ldc + n0 + tx * 8;
            *(float4*)Cr = o0;
            *(float4*)(Cr + 4) = o1;
        }
    }
}

struct Batch3 {
    const float* A[3]; const float* B[3]; const float* bias[3]; float* C[3];
};

__global__ void __launch_bounds__(256, 2) gemm128_batched(
    Batch3 bt, int lda, int ldb, int ldc, int K)
{
    __shared__ float As[2 * 16 * 128];
    __shared__ float Bs[2 * 16 * 128];
    int z = blockIdx.z;
    gemm128_body(bt.A[z], lda, bt.B[z], ldb, bt.bias[z], bt.C[z],
                 nullptr, 1.0f, ldc, K, As, Bs);
}

__global__ void __launch_bounds__(256, 2) gemm128_qer(
    const float* __restrict__ qp, const float* __restrict__ E,
    __half* __restrict__ qer16)
{
    __shared__ float As[2 * 16 * 128];
    __shared__ float Bs[2 * 16 * 128];
    int z = blockIdx.z, b = z >> 3, h = z & 7;
    gemm128_body(qp + ((size_t)b * SEQ) * DIM + h * DEPTH, DIM,
                 E + h * DEPTH, DIM, nullptr,
                 nullptr, qer16 + (size_t)z * SEQ * 1024, C1,
                 1024, DEPTH, As, Bs);
}

// ---------------- mask -> bitfield (1 bit per logit, 2 MB total) -------------
__global__ void __launch_bounds__(256) maskbits(
    const int* __restrict__ mask, uint32_t* __restrict__ mb)
{
    size_t w = (size_t)blockIdx.x * 256 + threadIdx.x;   // word over NB*SEQ*64
    const int4* src = (const int4*)mask + w * 8;
    uint32_t bits = 0;
    #pragma unroll
    for (int l = 0; l < 8; l++) {
        int4 m = src[l];
        bits |= (m.x ? 1u : 0u) << (l * 4 + 0);
        bits |= (m.y ? 1u : 0u) << (l * 4 + 1);
        bits |= (m.z ? 1u : 0u) << (l * 4 + 2);
        bits |= (m.w ? 1u : 0u) << (l * 4 + 3);
    }
    mb[w] = bits;
}

// ---------------- inline-skew window loaders ----------------------------------
__device__ __forceinline__ uint32_t duph(const __half* p) {
    uint32_t u = (uint32_t)__half_as_ushort(*p);
    return u | (u << 16);
}
// 4 consecutive halfs at row+idx via two aligned 8B loads + funnel shift.
__device__ __forceinline__ uint2 win4(const __half* row, int idx) {
    uintptr_t a = (uintptr_t)(row + idx);
    const uint2* a8 = (const uint2*)(a & ~(uintptr_t)7);
    uint2 L = a8[0], H = a8[1];
    int sh = (int)(a & 7) * 8;         // 0,16,32,48
    uint32_t x0 = L.x, x1 = L.y, x2 = H.x;
    if (sh & 32) { x0 = L.y; x1 = H.x; x2 = H.y; }
    sh &= 31;                          // 0 or 16
    uint2 r;
    r.x = __funnelshift_r(x0, x1, sh);
    r.y = __funnelshift_r(x1, x2, sh);
    return r;
}
// ADD values (pre-scaled by C1, no mask) for 4 logits q=qs..qs+3 of row p.
__device__ __forceinline__ uint2 grp4(const __half* qer_p, const __half* qer_p1,
                                      int qs, int p) {
    int d = qs - p;
    if (d + 3 <= 0) {                        // all q <= p
        int idx = d + 1023;
        if (idx >= 0) return win4(qer_p, idx);
        if (idx + 3 < 0) { uint32_t v = duph(qer_p); return make_uint2(v, v); }
    } else if (d >= 2) {                     // all q >= p+2
        int idx = d - 1026;
        if (idx >= 0) return win4(qer_p1, idx);
        if (idx + 3 < 0) { uint32_t v = duph(qer_p1); return make_uint2(v, v); }
    }
    // rare: straddles the diagonal or a clamp boundary
    unsigned short h[4];
    #pragma unroll
    for (int l = 0; l < 4; l++) {
        int dd = d + l;
        __half s;
        if (dd <= 0)       s = qer_p[max(dd + 1023, 0)];
        else if (dd == 1)  s = __ushort_as_half((unsigned short)0);
        else               s = qer_p1[max(dd - 1026, 0)];
        h[l] = __half_as_ushort(s);
    }
    return make_uint2((uint32_t)h[0] | ((uint32_t)h[1] << 16),
                      (uint32_t)h[2] | ((uint32_t)h[3] << 16));
}

// ---------------- fused flash attention: inline skew + bitmask ---------------
__global__ void __launch_bounds__(256, 1) attn_kernel(
    const float* __restrict__ qp, const float* __restrict__ kp,
    const float* __restrict__ vp, const __half* __restrict__ qer16,
    const uint32_t* __restrict__ mb, float* __restrict__ out)
{
    extern __shared__ float sm[];
    float* Qts = sm;                 // 64*128
    float* KPs = sm + 64 * 128;      // 128*128 (K^T first 64 rows; then P^T)
    float* Vs  = sm + 64 * 128 + 128 * 128;   // 128*64

    const int tid = threadIdx.x;
    const int tx = tid & 15, ty = tid >> 4;
    const int p0 = blockIdx.x * 128;
    const int h = blockIdx.y, b = blockIdx.z;

    const float* Qg = qp + ((size_t)b * SEQ) * DIM + h * DEPTH;
    const float* Kg = kp + ((size_t)b * SEQ) * DIM + h * DEPTH;
    const float* Vg = vp + ((size_t)b * SEQ) * DIM + h * DEPTH;
    const __half* qer16b = qer16 + ((size_t)(b * NH + h)) * SEQ * 1024;
    const uint32_t* mbb = mb + (size_t)b * SEQ * 64;

    const int lq4 = (tid & 31) * 4;
    const int ld8 = (tid >> 5) * 8;
    const int vd4 = (tid & 15) * 4;
    const int vq8 = (tid >> 4) * 8;
    uint32_t vs_u32 = s2u(&Vs[(vq8)*64 + vd4]);

    int pl[8];
    #pragma unroll
    for (int i = 0; i < 8; i++) pl[i] = (i < 4) ? ty * 4 + i : 64 + ty * 4 + (i - 4);

    // ---- stage Q^T once ------------------------------------------------------
    {
        float4 qf[4][2];
        #pragma unroll
        for (int r = 0; r < 4; r++)
            #pragma unroll
            for (int c2 = 0; c2 < 2; c2++)
                qf[r][c2] = *(const float4*)(Qg + (size_t)(p0 + lq4 + r) * DIM + ld8 + c2 * 4);
        const float* qfl = (const float*)qf;
        #pragma unroll
        for (int m = 0; m < 8; m++) {
            float4 t = {qfl[0 * 8 + m], qfl[1 * 8 + m], qfl[2 * 8 + m], qfl[3 * 8 + m]};
            *(float4*)&Qts[(ld8 + m) * 128 + lq4] = t;
        }
    }

    u64 acc[8][2];
    float lsum[8];
    #pragma unroll
    for (int i = 0; i < 8; i++) { lsum[i] = 0.0f; acc[i][0] = 0ull; acc[i][1] = 0ull; }

    // ---- prologue: tile 0 K into regs ---------------------------------------
    float4 kf[4][2];
    #pragma unroll
    for (int r = 0; r < 4; r++)
        #pragma unroll
        for (int c2 = 0; c2 < 2; c2++)
            kf[r][c2] = *(const float4*)(Kg + (size_t)(lq4 + r) * DIM + ld8 + c2 * 4);

    for (int q0 = 0; q0 < SEQ; q0 += 128) {
        __syncthreads();   // prior tile's PV readers done with KPs/Vs
        {
            const float* kfl = (const float*)kf;
            #pragma unroll
            for (int m = 0; m < 8; m++) {
                float4 t = {kfl[0 * 8 + m], kfl[1 * 8 + m], kfl[2 * 8 + m], kfl[3 * 8 + m]};
                *(float4*)&KPs[(ld8 + m) * 128 + lq4] = t;
            }
            #pragma unroll
            for (int r = 0; r < 8; r++)
                cpasync16(vs_u32 + r * 64 * 4,
                          Vg + (size_t)(q0 + vq8 + r) * DIM + vd4);
            asm volatile("cp.async.commit_group;");
        }
        __syncthreads();

        // ---- inline skew gather + mask bits (hidden under S-GEMM below) ----
        uint2 adu[8][2];
        uint32_t nib[8];
        #pragma unroll
        for (int i = 0; i < 8; i++) {
            const int p = p0 + pl[i];
            const __half* qer_p  = qer16b + (size_t)p * 1024;
            const __half* qer_p1 = qer16b + (size_t)min(p + 1, SEQ - 1) * 1024;
            adu[i][0] = grp4(qer_p, qer_p1, q0 + tx * 4, p);
            adu[i][1] = grp4(qer_p, qer_p1, q0 + 64 + tx * 4, p);
            const uint32_t* mrow = mbb + (size_t)p * 64 + (q0 >> 5) + (tx >> 3);
            uint32_t w1 = mrow[0], w2 = mrow[2];
            int shm = (tx * 4) & 31;
            nib[i] = ((w1 >> shm) & 0xFu) | (((w2 >> shm) & 0xFu) << 4);
        }

        // ---- prefetch NEXT tile's K -----------------------------------------
        if (q0 + 128 < SEQ) {
            const int qn = q0 + 128;
            #pragma unroll
            for (int r = 0; r < 4; r++)
                #pragma unroll
                for (int c2 = 0; c2 < 2; c2++)
                    kf[r][c2] = *(const float4*)(Kg + (size_t)(qn + lq4 + r) * DIM + ld8 + c2 * 4);
        }

        // ---- S = Q K^T : 128x128x64, 8x8/thread ---------------------------
        u64 sv[8][4];
        #pragma unroll
        for (int i = 0; i < 8; i++)
            #pragma unroll
            for (int j = 0; j < 4; j++) sv[i][j] = 0ull;
        #pragma unroll 4
        for (int kk = 0; kk < 64; kk++) {
            float4 a0 = *(const float4*)&Qts[kk * 128 + ty * 4];
            float4 a1 = *(const float4*)&Qts[kk * 128 + 64 + ty * 4];
            float4 b0 = *(const float4*)&KPs[kk * 128 + tx * 4];
            float4 b1 = *(const float4*)&KPs[kk * 128 + 64 + tx * 4];
            u64 bp0 = pk(b0.x, b0.y), bp1 = pk(b0.z, b0.w);
            u64 bp2 = pk(b1.x, b1.y), bp3 = pk(b1.z, b1.w);
            float av[8] = {a0.x, a0.y, a0.z, a0.w, a1.x, a1.y, a1.z, a1.w};
            #pragma unroll
            for (int i = 0; i < 8; i++) {
                u64 as = pk(av[i], av[i]);
                fma2(sv[i][0], as, bp0);
                fma2(sv[i][1], as, bp1);
                fma2(sv[i][2], as, bp2);
                fma2(sv[i][3], as, bp3);
            }
        }

        __syncthreads();  // all S reads of KPs done before P^T overwrite
        // ---- exp fused into P^T store (column-wise); masked -> weight 0 ----
        {
            const int swc = ((ty ^ (tx & 7)) << 2);
            #pragma unroll
            for (int j = 0; j < 8; j++) {
                float e[8];
                #pragma unroll
                for (int i = 0; i < 8; i++) {
                    float2 x = up(sv[i][j >> 1]);
                    float s = (j & 1) ? x.y : x.x;
                    __half2 hw = ((const __half2*)&adu[i][j >> 2])[(j >> 1) & 1];
                    float a = (j & 1) ? __high2float(hw) : __low2float(hw);
                    float y = fmaf(s, C1, a);
                    float ev = fexp2(y);
                    ev = ((nib[i] >> j) & 1u) ? 0.0f : ev;
                    e[i] = ev;
                    lsum[i] += ev;
                }
                int ql = (j < 4) ? tx * 4 + j : 64 + tx * 4 + (j - 4);
                float4 t0 = {e[0], e[1], e[2], e[3]};
                float4 t1 = {e[4], e[5], e[6], e[7]};
                *(float4*)&KPs[ql * 128 + swc] = t0;
                *(float4*)&KPs[ql * 128 + 64 + swc] = t1;
            }
        }
        asm volatile("cp.async.wait_group 0;" ::: "memory");
        __syncthreads();   // P^T + V visible to all

        // ---- O += P V : 128x64x128, 8x4/thread ----------------------------
        for (int kc = 0; kc < 32; kc++) {
            const int sw2 = ((ty ^ (kc & 7)) << 2);
            const int kb = kc * 4;
            #pragma unroll
            for (int l = 0; l < 4; l++) {
                const int kk = kb + l;
                float4 a0 = *(const float4*)&KPs[kk * 128 + sw2];
                float4 a1 = *(const float4*)&KPs[kk * 128 + 64 + sw2];
                float4 bv = *(const float4*)&Vs[kk * 64 + tx * 4];
                u64 bp0 = pk(bv.x, bv.y), bp1 = pk(bv.z, bv.w);
                float av[8] = {a0.x, a0.y, a0.z, a0.w, a1.x, a1.y, a1.z, a1.w};
                #pragma unroll
                for (int i = 0; i < 8; i++) {
                    u64 as = pk(av[i], av[i]);
                    fma2(acc[i][0], as, bp0);
                    fma2(acc[i][1], as, bp1);
                }
            }
        }
    }

    // ---- final row-sum reduction (once) and store ------------------------
    #pragma unroll
    for (int i = 0; i < 8; i++) {
        #pragma unroll
        for (int o = 8; o >= 1; o >>= 1)
            lsum[i] += __shfl_xor_sync(0xffffffffu, lsum[i], o);
        float inv = 1.0f / lsum[i];
        float2 c0 = up(acc[i][0]), c1 = up(acc[i][1]);
        float4 o0 = {c0.x * inv, c0.y * inv, c1.x * inv, c1.y * inv};
        *(float4*)&out[((size_t)b * SEQ + p0 + pl[i]) * DIM + h * DEPTH + tx * 4] = o0;
    }
}

// ---------------- launch ------------------------------------------------------
extern "C" void kernel_launch(void* const* d_in, const int* in_sizes, int n_in,
                              void* d_out, int out_size) {
    const float* q    = (const float*)d_in[0];
    const float* k    = (const float*)d_in[1];
    const float* v    = (const float*)d_in[2];
    const int*   mask = (const int*)  d_in[3];
    const float* Wq_w = (const float*)d_in[4];
    const float* Wq_b = (const float*)d_in[5];
    const float* Wk_w = (const float*)d_in[6];
    const float* Wk_b = (const float*)d_in[7];
    const float* Wv_w = (const float*)d_in[8];
    const float* Wv_b = (const float*)d_in[9];
    const float* E    = (const float*)d_in[10];
    const float* Wo_w = (const float*)d_in[11];
    const float* Wo_b = (const float*)d_in[12];

    float *qp, *kp, *vp, *attn;
    __half* qer16;
    uint32_t* mb;
    cudaGetSymbolAddress((void**)&qp,    g_qp);
    cudaGetSymbolAddress((void**)&kp,    g_kp);
    cudaGetSymbolAddress((void**)&vp,    g_vp);
    cudaGetSymbolAddress((void**)&attn,  g_attn);
    cudaGetSymbolAddress((void**)&qer16, g_qer16);
    cudaGetSymbolAddress((void**)&mb,    g_mb);

    dim3 blk(256);

    // 0) mask -> bitfield (independent; tiny)
    maskbits<<<(NB * SEQ * 64) / 256, 256>>>(mask, mb);

    // 1) q/k/v projections (batched, double-buffered)
    Batch3 pb;
    pb.A[0] = q;  pb.B[0] = Wq_w; pb.bias[0] = Wq_b; pb.C[0] = qp;
    pb.A[1] = k;  pb.B[1] = Wk_w; pb.bias[1] = Wk_b; pb.C[1] = kp;
    pb.A[2] = v;  pb.B[2] = Wv_w; pb.bias[2] = Wv_b; pb.C[2] = vp;
    gemm128_batched<<<dim3(DIM / 128, (NB * SEQ) / 128, 3), blk>>>(pb, DIM, DIM, DIM, DIM);

    // 2) QEr (16 z-slices) -> fp16 with C1 folded
    gemm128_qer<<<dim3(1024 / 128, SEQ / 128, NB * NH), blk>>>(qp, E, qer16);

    // 3) fused attention (inline skew + bitmask; no ADD tensor)
    const int ATTN_SMEM = (64 * 128 + 128 * 128 + 128 * 64) * 4;  // 128 KB
    cudaFuncSetAttribute(attn_kernel, cudaFuncAttributeMaxDynamicSharedMemorySize, ATTN_SMEM);
    attn_kernel<<<dim3(SEQ / 128, NH, NB), blk, ATTN_SMEM>>>(qp, kp, vp, qer16, mb, attn);

    // 4) output projection -> d_out
    Batch3 ob;
    ob.A[0] = attn; ob.B[0] = Wo_w; ob.bias[0] = Wo_b; ob.C[0] = (float*)d_out;
    gemm128_batched<<<dim3(DIM / 128, (NB * SEQ) / 128, 1), blk>>>(ob, DIM, DIM, DIM, DIM);
}

// round 15
// speedup vs baseline: 1.1895x; 1.1895x over previous
#include <cuda_runtime.h>
#include <cuda_fp16.h>
#include <cstdint>

#define SEQ   2048
#define DIM   512
#define NH    8
#define DEPTH 64
#define NB    2
typedef unsigned long long u64;

#define C1    0.18033688011112043f     /* 0.125 * log2(e) */

// ---------------- scratch (device globals; no runtime allocation) ------------
__device__ float    g_qp[(size_t)NB * SEQ * DIM];
__device__ float    g_kp[(size_t)NB * SEQ * DIM];
__device__ float    g_vp[(size_t)NB * SEQ * DIM];
__device__ float    g_attn[(size_t)NB * SEQ * DIM];
__device__ __half   g_qer16[(size_t)NB * NH * SEQ * 1024];  // 64 MB (C1 pre-folded)
__device__ __half   g_add[(size_t)NB * NH * SEQ * SEQ];     // 128 MB (fp16)
__device__ uint32_t g_mb[(size_t)NB * SEQ * (SEQ / 32)];    // 2 MB mask bits

// ---------------- packed fp32x2 helpers (FFMA2: 2x fp32 throughput) ----------
__device__ __forceinline__ u64 pk(float lo, float hi) {
    u64 r; asm("mov.b64 %0,{%1,%2};" : "=l"(r) : "f"(lo), "f"(hi)); return r;
}
__device__ __forceinline__ void fma2(u64& d, u64 a, u64 b) {
    asm("fma.rn.f32x2 %0,%1,%2,%0;" : "+l"(d) : "l"(a), "l"(b));
}
__device__ __forceinline__ float2 up(u64 v) {
    float2 r; asm("mov.b64 {%0,%1},%2;" : "=f"(r.x), "=f"(r.y) : "l"(v)); return r;
}
__device__ __forceinline__ uint32_t s2u(const void* p) {
    uint32_t a;
    asm("{ .reg .u64 t; cvta.to.shared.u64 t, %1; cvt.u32.u64 %0, t; }"
        : "=r"(a) : "l"(p));
    return a;
}
__device__ __forceinline__ void cpasync16(uint32_t sm, const void* g) {
    asm volatile("cp.async.cg.shared.global [%0], [%1], 16;" :: "r"(sm), "l"(g));
}

// ---------------- fast exp2 on the FMA pipe (no MUFU, no F2I) ----------------
__device__ __forceinline__ float fexp2(float y) {
    float t = y + 12582912.0f;           // 1.5 * 2^23 : round-to-nearest int
    float r = t - 12582912.0f;
    float f = y - r;                     // f in [-0.5, 0.5]
    float p = 1.3333558146e-3f;
    p = fmaf(p, f, 9.6181291076e-3f);
    p = fmaf(p, f, 5.5504108664e-2f);
    p = fmaf(p, f, 2.4022650696e-1f);
    p = fmaf(p, f, 6.9314718056e-1f);
    p = fmaf(p, f, 1.0f);
    int R = __float_as_int(t) - 0x4B400000;         // = (int)r
    return p * __int_as_float((R + 127) << 23);
}

// ---------------- 128x128 NT GEMM body, 8x8 microtile, double-buffered -------
__device__ __forceinline__ void gemm128_body(
    const float* __restrict__ A, int lda,
    const float* __restrict__ B, int ldb,
    const float* __restrict__ bias,
    float* __restrict__ C, __half* __restrict__ C16, float cscale,
    int ldc, int K, float* As, float* Bs)
{
    const int tid = threadIdx.x;
    const int tx = tid & 15, ty = tid >> 4;
    const int m0 = blockIdx.y * 128, n0 = blockIdx.x * 128;
    const int lrow = tid >> 2, lc4 = (tid & 3) * 4;
    const float* Ag = A + (size_t)(m0 + lrow) * lda + lc4;
    const float* Bg = B + (size_t)(n0 + lrow) * ldb + lc4;

    u64 acc[8][4];
    #pragma unroll
    for (int i = 0; i < 8; i++)
        #pragma unroll
        for (int j = 0; j < 4; j++) acc[i][j] = 0ull;

    float4 a0 = *(const float4*)(Ag);
    float4 a1 = *(const float4*)(Ag + (size_t)64 * lda);
    float4 b0 = *(const float4*)(Bg);
    float4 b1 = *(const float4*)(Bg + (size_t)64 * ldb);

    As[(lc4 + 0) * 128 + lrow] = a0.x; As[(lc4 + 1) * 128 + lrow] = a0.y;
    As[(lc4 + 2) * 128 + lrow] = a0.z; As[(lc4 + 3) * 128 + lrow] = a0.w;
    As[(lc4 + 0) * 128 + lrow + 64] = a1.x; As[(lc4 + 1) * 128 + lrow + 64] = a1.y;
    As[(lc4 + 2) * 128 + lrow + 64] = a1.z; As[(lc4 + 3) * 128 + lrow + 64] = a1.w;
    Bs[(lc4 + 0) * 128 + lrow] = b0.x; Bs[(lc4 + 1) * 128 + lrow] = b0.y;
    Bs[(lc4 + 2) * 128 + lrow] = b0.z; Bs[(lc4 + 3) * 128 + lrow] = b0.w;
    Bs[(lc4 + 0) * 128 + lrow + 64] = b1.x; Bs[(lc4 + 1) * 128 + lrow + 64] = b1.y;
    Bs[(lc4 + 2) * 128 + lrow + 64] = b1.z; Bs[(lc4 + 3) * 128 + lrow + 64] = b1.w;
    __syncthreads();

    const int nk = K >> 4;
    for (int it = 0; it < nk; it++) {
        const int cb = (it & 1) << 11;
        if (it + 1 < nk) {
            int k0 = (it + 1) << 4;
            a0 = *(const float4*)(Ag + k0);
            a1 = *(const float4*)(Ag + (size_t)64 * lda + k0);
            b0 = *(const float4*)(Bg + k0);
            b1 = *(const float4*)(Bg + (size_t)64 * ldb + k0);
        }
        #pragma unroll
        for (int kk = 0; kk < 16; kk++) {
            float4 x0 = *(const float4*)&As[cb + kk * 128 + ty * 8];
            float4 x1 = *(const float4*)&As[cb + kk * 128 + ty * 8 + 4];
            float4 y0 = *(const float4*)&Bs[cb + kk * 128 + tx * 8];
            float4 y1 = *(const float4*)&Bs[cb + kk * 128 + tx * 8 + 4];
            u64 bp0 = pk(y0.x, y0.y), bp1 = pk(y0.z, y0.w);
            u64 bp2 = pk(y1.x, y1.y), bp3 = pk(y1.z, y1.w);
            float av[8] = {x0.x, x0.y, x0.z, x0.w, x1.x, x1.y, x1.z, x1.w};
            #pragma unroll
            for (int i = 0; i < 8; i++) {
                u64 as = pk(av[i], av[i]);
                fma2(acc[i][0], as, bp0);
                fma2(acc[i][1], as, bp1);
                fma2(acc[i][2], as, bp2);
                fma2(acc[i][3], as, bp3);
            }
        }
        if (it + 1 < nk) {
            const int nb = ((it + 1) & 1) << 11;
            As[nb + (lc4 + 0) * 128 + lrow] = a0.x; As[nb + (lc4 + 1) * 128 + lrow] = a0.y;
            As[nb + (lc4 + 2) * 128 + lrow] = a0.z; As[nb + (lc4 + 3) * 128 + lrow] = a0.w;
            As[nb + (lc4 + 0) * 128 + lrow + 64] = a1.x; As[nb + (lc4 + 1) * 128 + lrow + 64] = a1.y;
            As[nb + (lc4 + 2) * 128 + lrow + 64] = a1.z; As[nb + (lc4 + 3) * 128 + lrow + 64] = a1.w;
            Bs[nb + (lc4 + 0) * 128 + lrow] = b0.x; Bs[nb + (lc4 + 1) * 128 + lrow] = b0.y;
            Bs[nb + (lc4 + 2) * 128 + lrow] = b0.z; Bs[nb + (lc4 + 3) * 128 + lrow] = b0.w;
            Bs[nb + (lc4 + 0) * 128 + lrow + 64] = b1.x; Bs[nb + (lc4 + 1) * 128 + lrow + 64] = b1.y;
            Bs[nb + (lc4 + 2) * 128 + lrow + 64] = b1.z; Bs[nb + (lc4 + 3) * 128 + lrow + 64] = b1.w;
            __syncthreads();
        }
    }

    if (C16) {
        #pragma unroll
        for (int i = 0; i < 8; i++) {
            float2 c0 = up(acc[i][0]), c1 = up(acc[i][1]);
            float2 c2 = up(acc[i][2]), c3 = up(acc[i][3]);
            __half2 h0 = __floats2half2_rn(c0.x * cscale, c0.y * cscale);
            __half2 h1 = __floats2half2_rn(c1.x * cscale, c1.y * cscale);
            __half2 h2 = __floats2half2_rn(c2.x * cscale, c2.y * cscale);
            __half2 h3 = __floats2half2_rn(c3.x * cscale, c3.y * cscale);
            uint4 o;
            o.x = *(uint32_t*)&h0; o.y = *(uint32_t*)&h1;
            o.z = *(uint32_t*)&h2; o.w = *(uint32_t*)&h3;
            *(uint4*)(C16 + (size_t)(m0 + ty * 8 + i) * ldc + n0 + tx * 8) = o;
        }
    } else {
        float bj[8];
        #pragma unroll
        for (int j = 0; j < 8; j++) bj[j] = bias ? bias[n0 + tx * 8 + j] : 0.0f;
        #pragma unroll
        for (int i = 0; i < 8; i++) {
            float2 c0 = up(acc[i][0]), c1 = up(acc[i][1]);
            float2 c2 = up(acc[i][2]), c3 = up(acc[i][3]);
            float4 o0 = {c0.x + bj[0], c0.y + bj[1], c1.x + bj[2], c1.y + bj[3]};
            float4 o1 = {c2.x + bj[4], c2.y + bj[5], c3.x + bj[6], c3.y + bj[7]};
            float* Cr = C + (size_t)(m0 + ty * 8 + i) * ldc + n0 + tx * 8;
            *(float4*)Cr = o0;
            *(float4*)(Cr + 4) = o1;
        }
    }
}

struct Batch3 {
    const float* A[3]; const float* B[3]; const float* bias[3]; float* C[3];
};

__global__ void __launch_bounds__(256, 2) gemm128_batched(
    Batch3 bt, int lda, int ldb, int ldc, int K)
{
    __shared__ float As[2 * 16 * 128];
    __shared__ float Bs[2 * 16 * 128];
    int z = blockIdx.z;
    gemm128_body(bt.A[z], lda, bt.B[z], ldb, bt.bias[z], bt.C[z],
                 nullptr, 1.0f, ldc, K, As, Bs);
}

__global__ void __launch_bounds__(256, 2) gemm128_qer(
    const float* __restrict__ qp, const float* __restrict__ E,
    __half* __restrict__ qer16)
{
    __shared__ float As[2 * 16 * 128];
    __shared__ float Bs[2 * 16 * 128];
    int z = blockIdx.z, b = z >> 3, h = z & 7;
    gemm128_body(qp + ((size_t)b * SEQ) * DIM + h * DEPTH, DIM,
                 E + h * DEPTH, DIM, nullptr,
                 nullptr, qer16 + (size_t)z * SEQ * 1024, C1,
                 1024, DEPTH, As, Bs);
}

// ---------------- mask -> bitfield (1 bit per logit, 2 MB total) -------------
__global__ void __launch_bounds__(256) maskbits(
    const int* __restrict__ mask, uint32_t* __restrict__ mb)
{
    size_t w = (size_t)blockIdx.x * 256 + threadIdx.x;   // word over NB*SEQ*64
    const int4* src = (const int4*)mask + w * 8;
    uint32_t bits = 0;
    #pragma unroll
    for (int l = 0; l < 8; l++) {
        int4 m = src[l];
        bits |= (m.x ? 1u : 0u) << (l * 4 + 0);
        bits |= (m.y ? 1u : 0u) << (l * 4 + 1);
        bits |= (m.z ? 1u : 0u) << (l * 4 + 2);
        bits |= (m.w ? 1u : 0u) << (l * 4 + 3);
    }
    mb[w] = bits;
}

// ---------------- ADD[p][q]: bit-copy of qer16 / -3000 where masked ----------
// 8 consecutive p per block: qer row p+1 is touched by branch-1 (row p+1) and
// branch-2 (row p) inside the same block -> L1-served second read.
// Mask comes from the 2 MB bitfield (1 LDG.32 per 32 logits).
__global__ void __launch_bounds__(512) build_add(
    const __half* __restrict__ qer16, const uint32_t* __restrict__ mb,
    __half* __restrict__ add)
{
    const int p8 = blockIdx.x * 8;
    const int z = blockIdx.y;           // b*8 + h
    const int b = z >> 3;
    const int q = threadIdx.x * 4;
    const unsigned short hmask = __half_as_ushort(__float2half(-3000.0f));
    const int widx = threadIdx.x >> 3;          // q >> 5
    const int nsh  = (threadIdx.x & 7) * 4;     // q & 31
    #pragma unroll
    for (int r = 0; r < 8; r++) {
        const int p = p8 + r;
        const __half* qer_p  = qer16 + ((size_t)z * SEQ + p) * 1024;
        const __half* qer_p1 = qer_p + 1024;
        uint32_t nib = (mb[((size_t)b * SEQ + p) * 64 + widx] >> nsh) & 0xFu;
        unsigned short op[4];
        #pragma unroll
        for (int l = 0; l < 4; l++) {
            int qq = q + l;
            unsigned short s;
            if (qq <= p)            s = __half_as_ushort(qer_p[max(qq - p + 1023, 0)]);
            else if (qq == p + 1)   s = 0;
            else                    s = __half_as_ushort(qer_p1[max(qq - p - 1026, 0)]);
            op[l] = (nib & (1u << l)) ? hmask : s;
        }
        uint2 ov;
        ov.x = (uint32_t)op[0] | ((uint32_t)op[1] << 16);
        ov.y = (uint32_t)op[2] | ((uint32_t)op[3] << 16);
        *(uint2*)(add + ((size_t)z * SEQ + p) * SEQ + q) = ov;
    }
}

// ---------------- fused flash attention (R9/R13 form: best measured) ---------
__global__ void __launch_bounds__(256, 1) attn_kernel(
    const float* __restrict__ qp, const float* __restrict__ kp,
    const float* __restrict__ vp, const __half* __restrict__ add,
    float* __restrict__ out)
{
    extern __shared__ float sm[];
    float* Qts = sm;                 // 64*128
    float* KPs = sm + 64 * 128;      // 128*128 (K^T first 64 rows; then P^T)
    float* Vs  = sm + 64 * 128 + 128 * 128;   // 128*64

    const int tid = threadIdx.x;
    const int tx = tid & 15, ty = tid >> 4;
    const int p0 = blockIdx.x * 128;
    const int h = blockIdx.y, b = blockIdx.z;

    const float* Qg = qp + ((size_t)b * SEQ) * DIM + h * DEPTH;
    const float* Kg = kp + ((size_t)b * SEQ) * DIM + h * DEPTH;
    const float* Vg = vp + ((size_t)b * SEQ) * DIM + h * DEPTH;
    const __half* addb = add + ((size_t)(b * NH + h)) * SEQ * SEQ;

    const int lq4 = (tid & 31) * 4;
    const int ld8 = (tid >> 5) * 8;
    const int vd4 = (tid & 15) * 4;
    const int vq8 = (tid >> 4) * 8;
    uint32_t vs_u32 = s2u(&Vs[(vq8)*64 + vd4]);

    int pl[8];
    #pragma unroll
    for (int i = 0; i < 8; i++) pl[i] = (i < 4) ? ty * 4 + i : 64 + ty * 4 + (i - 4);

    // ---- stage Q^T once ------------------------------------------------------
    {
        float4 qf[4][2];
        #pragma unroll
        for (int r = 0; r < 4; r++)
            #pragma unroll
            for (int c2 = 0; c2 < 2; c2++)
                qf[r][c2] = *(const float4*)(Qg + (size_t)(p0 + lq4 + r) * DIM + ld8 + c2 * 4);
        const float* qfl = (const float*)qf;
        #pragma unroll
        for (int m = 0; m < 8; m++) {
            float4 t = {qfl[0 * 8 + m], qfl[1 * 8 + m], qfl[2 * 8 + m], qfl[3 * 8 + m]};
            *(float4*)&Qts[(ld8 + m) * 128 + lq4] = t;
        }
    }

    u64 acc[8][2];
    float lsum[8];
    #pragma unroll
    for (int i = 0; i < 8; i++) { lsum[i] = 0.0f; acc[i][0] = 0ull; acc[i][1] = 0ull; }

    // ---- prologue prefetch: tile 0 K and ADD into regs ----------------------
    float4 kf[4][2];
    uint2 adu[8][2], adu2[8][2];
    #pragma unroll
    for (int r = 0; r < 4; r++)
        #pragma unroll
        for (int c2 = 0; c2 < 2; c2++)
            kf[r][c2] = *(const float4*)(Kg + (size_t)(lq4 + r) * DIM + ld8 + c2 * 4);
    #pragma unroll
    for (int i = 0; i < 8; i++) {
        const __half* arow = addb + (size_t)(p0 + pl[i]) * SEQ;
        adu[i][0] = *(const uint2*)(arow + tx * 4);
        adu[i][1] = *(const uint2*)(arow + 64 + tx * 4);
    }

    for (int q0 = 0; q0 < SEQ; q0 += 128) {
        __syncthreads();   // prior tile's PV readers done with KPs/Vs
        {
            const float* kfl = (const float*)kf;
            #pragma unroll
            for (int m = 0; m < 8; m++) {
                float4 t = {kfl[0 * 8 + m], kfl[1 * 8 + m], kfl[2 * 8 + m], kfl[3 * 8 + m]};
                *(float4*)&KPs[(ld8 + m) * 128 + lq4] = t;
            }
            #pragma unroll
            for (int r = 0; r < 8; r++)
                cpasync16(vs_u32 + r * 64 * 4,
                          Vg + (size_t)(q0 + vq8 + r) * DIM + vd4);
            asm volatile("cp.async.commit_group;");
        }
        __syncthreads();

        if (q0 + 128 < SEQ) {
            const int qn = q0 + 128;
            #pragma unroll
            for (int r = 0; r < 4; r++)
                #pragma unroll
                for (int c2 = 0; c2 < 2; c2++)
                    kf[r][c2] = *(const float4*)(Kg + (size_t)(qn + lq4 + r) * DIM + ld8 + c2 * 4);
            #pragma unroll
            for (int i = 0; i < 8; i++) {
                const __half* arow = addb + (size_t)(p0 + pl[i]) * SEQ + qn;
                adu2[i][0] = *(const uint2*)(arow + tx * 4);
                adu2[i][1] = *(const uint2*)(arow + 64 + tx * 4);
            }
        }

        // ---- S = Q K^T : 128x128x64, 8x8/thread ---------------------------
        u64 sv[8][4];
        #pragma unroll
        for (int i = 0; i < 8; i++)
            #pragma unroll
            for (int j = 0; j < 4; j++) sv[i][j] = 0ull;
        #pragma unroll 4
        for (int kk = 0; kk < 64; kk++) {
            float4 a0 = *(const float4*)&Qts[kk * 128 + ty * 4];
            float4 a1 = *(const float4*)&Qts[kk * 128 + 64 + ty * 4];
            float4 b0 = *(const float4*)&KPs[kk * 128 + tx * 4];
            float4 b1 = *(const float4*)&KPs[kk * 128 + 64 + tx * 4];
            u64 bp0 = pk(b0.x, b0.y), bp1 = pk(b0.z, b0.w);
            u64 bp2 = pk(b1.x, b1.y), bp3 = pk(b1.z, b1.w);
            float av[8] = {a0.x, a0.y, a0.z, a0.w, a1.x, a1.y, a1.z, a1.w};
            #pragma unroll
            for (int i = 0; i < 8; i++) {
                u64 as = pk(av[i], av[i]);
                fma2(sv[i][0], as, bp0);
                fma2(sv[i][1], as, bp1);
                fma2(sv[i][2], as, bp2);
                fma2(sv[i][3], as, bp3);
            }
        }

        __syncthreads();  // all S reads of KPs done before P^T overwrite
        // ---- exp fused into P^T store (column-wise) ------------------------
        {
            const int swc = ((ty ^ (tx & 7)) << 2);
            #pragma unroll
            for (int j = 0; j < 8; j++) {
                float e[8];
                #pragma unroll
                for (int i = 0; i < 8; i++) {
                    float2 x = up(sv[i][j >> 1]);
                    float s = (j & 1) ? x.y : x.x;
                    __half2 hw = ((const __half2*)&adu[i][j >> 2])[(j >> 1) & 1];
                    float a = (j & 1) ? __high2float(hw) : __low2float(hw);
                    float y = fmaf(s, C1, a);
                    y = fmaxf(y, -80.0f);
                    e[i] = fexp2(y);
                    lsum[i] += e[i];
                }
                int ql = (j < 4) ? tx * 4 + j : 64 + tx * 4 + (j - 4);
                float4 t0 = {e[0], e[1], e[2], e[3]};
                float4 t1 = {e[4], e[5], e[6], e[7]};
                *(float4*)&KPs[ql * 128 + swc] = t0;
                *(float4*)&KPs[ql * 128 + 64 + swc] = t1;
            }
        }
        asm volatile("cp.async.wait_group 0;" ::: "memory");
        __syncthreads();   // P^T + V visible to all

        // ---- O += P V : 128x64x128, 8x4/thread ----------------------------
        for (int kc = 0; kc < 32; kc++) {
            const int sw2 = ((ty ^ (kc & 7)) << 2);
            const int kb = kc * 4;
            #pragma unroll
            for (int l = 0; l < 4; l++) {
                const int kk = kb + l;
                float4 a0 = *(const float4*)&KPs[kk * 128 + sw2];
                float4 a1 = *(const float4*)&KPs[kk * 128 + 64 + sw2];
                float4 bv = *(const float4*)&Vs[kk * 64 + tx * 4];
                u64 bp0 = pk(bv.x, bv.y), bp1 = pk(bv.z, bv.w);
                float av[8] = {a0.x, a0.y, a0.z, a0.w, a1.x, a1.y, a1.z, a1.w};
                #pragma unroll
                for (int i = 0; i < 8; i++) {
                    u64 as = pk(av[i], av[i]);
                    fma2(acc[i][0], as, bp0);
                    fma2(acc[i][1], as, bp1);
                }
            }
        }

        // rotate ADD prefetch
        #pragma unroll
        for (int i = 0; i < 8; i++) { adu[i][0] = adu2[i][0]; adu[i][1] = adu2[i][1]; }
    }

    // ---- final row-sum reduction (once) and store ------------------------
    #pragma unroll
    for (int i = 0; i < 8; i++) {
        #pragma unroll
        for (int o = 8; o >= 1; o >>= 1)
            lsum[i] += __shfl_xor_sync(0xffffffffu, lsum[i], o);
        float inv = 1.0f / lsum[i];
        float2 c0 = up(acc[i][0]), c1 = up(acc[i][1]);
        float4 o0 = {c0.x * inv, c0.y * inv, c1.x * inv, c1.y * inv};
        *(float4*)&out[((size_t)b * SEQ + p0 + pl[i]) * DIM + h * DEPTH + tx * 4] = o0;
    }
}

// ---------------- launch ------------------------------------------------------
extern "C" void kernel_launch(void* const* d_in, const int* in_sizes, int n_in,
                              void* d_out, int out_size) {
    const float* q    = (const float*)d_in[0];
    const float* k    = (const float*)d_in[1];
    const float* v    = (const float*)d_in[2];
    const int*   mask = (const int*)  d_in[3];
    const float* Wq_w = (const float*)d_in[4];
    const float* Wq_b = (const float*)d_in[5];
    const float* Wk_w = (const float*)d_in[6];
    const float* Wk_b = (const float*)d_in[7];
    const float* Wv_w = (const float*)d_in[8];
    const float* Wv_b = (const float*)d_in[9];
    const float* E    = (const float*)d_in[10];
    const float* Wo_w = (const float*)d_in[11];
    const float* Wo_b = (const float*)d_in[12];

    float *qp, *kp, *vp, *attn;
    __half *qer16, *addp;
    uint32_t* mb;
    cudaGetSymbolAddress((void**)&qp,    g_qp);
    cudaGetSymbolAddress((void**)&kp,    g_kp);
    cudaGetSymbolAddress((void**)&vp,    g_vp);
    cudaGetSymbolAddress((void**)&attn,  g_attn);
    cudaGetSymbolAddress((void**)&qer16, g_qer16);
    cudaGetSymbolAddress((void**)&addp,  g_add);
    cudaGetSymbolAddress((void**)&mb,    g_mb);

    dim3 blk(256);

    // 0) mask -> bitfield (tiny)
    maskbits<<<(NB * SEQ * 64) / 256, 256>>>(mask, mb);

    // 1) q/k/v projections (batched, double-buffered)
    Batch3 pb;
    pb.A[0] = q;  pb.B[0] = Wq_w; pb.bias[0] = Wq_b; pb.C[0] = qp;
    pb.A[1] = k;  pb.B[1] = Wk_w; pb.bias[1] = Wk_b; pb.C[1] = kp;
    pb.A[2] = v;  pb.B[2] = Wv_w; pb.bias[2] = Wv_b; pb.C[2] = vp;
    gemm128_batched<<<dim3(DIM / 128, (NB * SEQ) / 128, 3), blk>>>(pb, DIM, DIM, DIM, DIM);

    // 2) QEr (16 z-slices) -> fp16 with C1 folded
    gemm128_qer<<<dim3(1024 / 128, SEQ / 128, NB * NH), blk>>>(qp, E, qer16);

    // 3) skew + mask-bits -> fp16 ADD (8 rows/block for qer L1 reuse)
    build_add<<<dim3(SEQ / 8, NB * NH), 512>>>(qer16, mb, addp);

    // 4) fused attention (R9/R13 pipelined form)
    const int ATTN_SMEM = (64 * 128 + 128 * 128 + 128 * 64) * 4;  // 128 KB
    cudaFuncSetAttribute(attn_kernel, cudaFuncAttributeMaxDynamicSharedMemorySize, ATTN_SMEM);
    attn_kernel<<<dim3(SEQ / 128, NH, NB), blk, ATTN_SMEM>>>(qp, kp, vp, addp, attn);

    // 5) output projection -> d_out
    Batch3 ob;
    ob.A[0] = attn; ob.B[0] = Wo_w; ob.bias[0] = Wo_b; ob.C[0] = (float*)d_out;
    gemm128_batched<<<dim3(DIM / 128, (NB * SEQ) / 128, 1), blk>>>(ob, DIM, DIM, DIM, DIM);
}